// round 5
// baseline (speedup 1.0000x reference)
#include <cuda_runtime.h>
#include <cuda_bf16.h>
#include <cstdint>

#define Nn 32768
#define Dd 512
#define Cc 64
#define Kk 16
#define Mm 512
#define Jj 256   // C*DEPTH
#define TAU 1e-3f
#define FLAG_CAP 131072

// ---------------- scratch ----------------
__device__ unsigned char d_idxT[Cc * Nn];            // [c][n]  2 MB
__device__ unsigned d_Lpk[64 * Cc * 32 * 4];         // packed B frags (bh0,bh1,bl0,bl1) 2 MB
__device__ unsigned d_flags[FLAG_CAP];
__device__ int d_flagCount;

__device__ __forceinline__ unsigned f2tf32(float f) {
    unsigned u;
    asm("cvt.rna.tf32.f32 %0, %1;" : "=r"(u) : "f"(f));
    return u;
}

// ---------------- K_pack: L -> packed bf16 hi/lo fragment layout; zero flag counter ----
__global__ void k_pack(const float* __restrict__ L) {
    if (blockIdx.x == 0 && threadIdx.x == 0) d_flagCount = 0;
    int i = blockIdx.x * 256 + threadIdx.x;        // pair index over 512*512
    int m = i >> 9;
    int k = (i & 511) * 2;
    float2 f = *(const float2*)&L[(size_t)m * 1024 + k];
    __nv_bfloat16 h0 = __float2bfloat16(f.x), h1 = __float2bfloat16(f.y);
    __nv_bfloat16 l0 = __float2bfloat16(f.x - __bfloat162float(h0));
    __nv_bfloat16 l1 = __float2bfloat16(f.y - __bfloat162float(h1));
    unsigned hv = ((unsigned)*(unsigned short*)&h1 << 16) | *(unsigned short*)&h0;
    unsigned lv = ((unsigned)*(unsigned short*)&l1 << 16) | *(unsigned short*)&l0;
    int c = k >> 4, kk = k & 15;
    int t4 = (kk >> 1) & 3, rb = kk >> 3;
    int lane = (m & 7) * 4 + t4, mt = m >> 3;
    unsigned* base = &d_Lpk[(((mt * Cc + c) * 32) + lane) * 4];
    base[rb] = hv;
    base[2 + rb] = lv;
}

// ---------------- K1: 3xTF32 mma GEMM (P = I @ A) + tree traversal -> idxT ----------------
#define MMA_TF32(d, a, b) \
    asm volatile("mma.sync.aligned.m16n8k8.row.col.f32.tf32.tf32.f32 " \
                 "{%0,%1,%2,%3},{%4,%5,%6,%7},{%8,%9},{%0,%1,%2,%3};" \
                 : "+f"(d[0]), "+f"(d[1]), "+f"(d[2]), "+f"(d[3]) \
                 : "r"(a[0]), "r"(a[1]), "r"(a[2]), "r"(a[3]), "r"(b[0]), "r"(b[1]))

#define G1_SMEM 49152

__global__ __launch_bounds__(256) void k_gemm_tf32(
    const float* __restrict__ I, const float* __restrict__ A,
    const float* __restrict__ Tg)
{
    extern __shared__ float sm1[];
    float* Ih = sm1;            // [mt4][ch4][lane32][reg4]
    float* Il = sm1 + 4096;
    float* Bh = sm1 + 8192;     // [n8 x8][ch4][lane32][reg2]
    float* Bl = sm1 + 10240;

    int tid = threadIdx.x, lane = tid & 31, wid = tid >> 5;
    int wm = wid & 1, wn = wid >> 1;
    int g = lane >> 2, t4 = lane & 3;
    int nBase = blockIdx.y * 128, jBase = blockIdx.x * 64;

    float acc[4][2][4];
#pragma unroll
    for (int mt = 0; mt < 4; mt++)
#pragma unroll
        for (int nt = 0; nt < 2; nt++)
#pragma unroll
            for (int q = 0; q < 4; q++) acc[mt][nt][q] = 0.f;

    for (int kt = 0; kt < Dd; kt += 32) {
        // stage I tile 128x32, hi/lo, fragment order
#pragma unroll
        for (int q = 0; q < 4; q++) {
            int idx = tid + q * 256;
            int row = idx >> 3, k4g = idx & 7;
            float4 v = *(const float4*)&I[(size_t)(nBase + row) * Dd + kt + k4g * 4];
            int mt = row >> 4, rb0 = (row >> 3) & 1, gg = row & 7;
            int ch = k4g >> 1, rb1 = k4g & 1;
            int reg = rb0 + 2 * rb1;
            int base = ((mt * 4 + ch) * 32 + gg * 4) * 4 + reg;
            float f[4] = {v.x, v.y, v.z, v.w};
#pragma unroll
            for (int e = 0; e < 4; e++) {
                unsigned uh = f2tf32(f[e]);
                float fh = __uint_as_float(uh);
                unsigned ul = f2tf32(f[e] - fh);
                Ih[base + e * 4] = fh;
                Il[base + e * 4] = __uint_as_float(ul);
            }
        }
        // stage A tile 32x64
#pragma unroll
        for (int q = 0; q < 2; q++) {
            int idx = tid + q * 256;
            int kr = idx >> 4, j4 = idx & 15;
            float4 v = *(const float4*)&A[(size_t)(kt + kr) * Jj + jBase + j4 * 4];
            int ch = kr >> 3, rb = (kr >> 2) & 1, tt = kr & 3;
            float f[4] = {v.x, v.y, v.z, v.w};
#pragma unroll
            for (int e = 0; e < 4; e++) {
                int n = j4 * 4 + e;
                int addr = (((n >> 3) * 4 + ch) * 32 + (n & 7) * 4 + tt) * 2 + rb;
                unsigned uh = f2tf32(f[e]);
                float fh = __uint_as_float(uh);
                Bh[addr] = fh;
                Bl[addr] = __uint_as_float(f2tf32(f[e] - fh));
            }
        }
        __syncthreads();

#pragma unroll
        for (int ch = 0; ch < 4; ch++) {
            unsigned ih[4][4], il[4][4], bh[2][2], bl[2][2];
#pragma unroll
            for (int mt = 0; mt < 4; mt++) {
                float4 vh = *(const float4*)&Ih[(((wm * 4 + mt) * 4 + ch) * 32 + lane) * 4];
                float4 vl = *(const float4*)&Il[(((wm * 4 + mt) * 4 + ch) * 32 + lane) * 4];
                ih[mt][0] = __float_as_uint(vh.x); ih[mt][1] = __float_as_uint(vh.y);
                ih[mt][2] = __float_as_uint(vh.z); ih[mt][3] = __float_as_uint(vh.w);
                il[mt][0] = __float_as_uint(vl.x); il[mt][1] = __float_as_uint(vl.y);
                il[mt][2] = __float_as_uint(vl.z); il[mt][3] = __float_as_uint(vl.w);
            }
#pragma unroll
            for (int nt = 0; nt < 2; nt++) {
                float2 vh = *(const float2*)&Bh[(((wn * 2 + nt) * 4 + ch) * 32 + lane) * 2];
                float2 vl = *(const float2*)&Bl[(((wn * 2 + nt) * 4 + ch) * 32 + lane) * 2];
                bh[nt][0] = __float_as_uint(vh.x); bh[nt][1] = __float_as_uint(vh.y);
                bl[nt][0] = __float_as_uint(vl.x); bl[nt][1] = __float_as_uint(vl.y);
            }
#pragma unroll
            for (int mt = 0; mt < 4; mt++)
#pragma unroll
                for (int nt = 0; nt < 2; nt++) {
                    MMA_TF32(acc[mt][nt], ih[mt], bh[nt]);
                    MMA_TF32(acc[mt][nt], il[mt], bh[nt]);
                    MMA_TF32(acc[mt][nt], ih[mt], bl[nt]);
                }
        }
        __syncthreads();
    }

    // ---- epilogue: P -> smem -> traverse ----
    float* Psm = sm1;   // [128][68]
#pragma unroll
    for (int mt = 0; mt < 4; mt++)
#pragma unroll
        for (int nt = 0; nt < 2; nt++) {
            int row = wm * 64 + mt * 16 + g;
            int col = wn * 16 + nt * 8 + t4 * 2;
            Psm[row * 68 + col]           = acc[mt][nt][0];
            Psm[row * 68 + col + 1]       = acc[mt][nt][1];
            Psm[(row + 8) * 68 + col]     = acc[mt][nt][2];
            Psm[(row + 8) * 68 + col + 1] = acc[mt][nt][3];
        }
    __syncthreads();

    int cb = tid & 15, r8 = tid >> 4;
    int c = blockIdx.x * 16 + cb;
    const float* Tc = &Tg[c * 15];
    unsigned long long pk = 0;
#pragma unroll
    for (int rr = 0; rr < 8; rr++) {
        float4 fv = *(const float4*)&Psm[(r8 * 8 + rr) * 68 + cb * 4];
        float f[4] = {fv.x, fv.y, fv.z, fv.w};
        unsigned node = 0, kidx = 0;
        float minabs = 1e30f;
#pragma unroll
        for (int l = 0; l < 4; l++) {
            float d = f[l] - __ldg(&Tc[node]);
            float ad = fabsf(d);
            minabs = (ad < minabs) ? ad : minabs;
            unsigned bit = (d > 0.f) ? 1u : 0u;
            kidx = (kidx << 1) | bit;
            node = 2 * node + 1 + bit;
        }
        pk |= (unsigned long long)kidx << (8 * rr);
        if (minabs < TAU) {
            int slot = atomicAdd(&d_flagCount, 1);
            if (slot < FLAG_CAP)
                d_flags[slot] = ((unsigned)(nBase + r8 * 8 + rr) << 6) | (unsigned)c;
        }
    }
    *(unsigned long long*)&d_idxT[(size_t)c * Nn + nBase + r8 * 8] = pk;
}

// ---------------- K1b: exact fp32 fixup for borderline codebooks ----------------
__global__ __launch_bounds__(256) void k_fixup(
    const float* __restrict__ I, const float* __restrict__ A,
    const float* __restrict__ Tg)
{
    int lane = threadIdx.x & 31;
    int wg = blockIdx.x * 8 + (threadIdx.x >> 5);
    int cnt = d_flagCount;
    if (cnt > FLAG_CAP) cnt = FLAG_CAP;
    for (int e = wg; e < cnt; e += 64 * 8) {
        unsigned v = d_flags[e];
        int n = v >> 6, c = v & 63;
        float a0 = 0.f, a1 = 0.f, a2 = 0.f, a3 = 0.f;
        for (int s = 0; s < 16; s++) {
            int k = s * 32 + lane;
            float iv = I[(size_t)n * Dd + k];
            float4 av = *(const float4*)&A[(size_t)k * Jj + c * 4];
            a0 = fmaf(iv, av.x, a0);
            a1 = fmaf(iv, av.y, a1);
            a2 = fmaf(iv, av.z, a2);
            a3 = fmaf(iv, av.w, a3);
        }
#pragma unroll
        for (int off = 16; off > 0; off >>= 1) {
            a0 += __shfl_xor_sync(0xffffffffu, a0, off);
            a1 += __shfl_xor_sync(0xffffffffu, a1, off);
            a2 += __shfl_xor_sync(0xffffffffu, a2, off);
            a3 += __shfl_xor_sync(0xffffffffu, a3, off);
        }
        if (lane == 0) {
            float f[4] = {a0, a1, a2, a3};
            const float* Tc = &Tg[c * 15];
            unsigned node = 0, kidx = 0;
#pragma unroll
            for (int l = 0; l < 4; l++) {
                unsigned bit = (f[l] > __ldg(&Tc[node])) ? 1u : 0u;
                kidx = (kidx << 1) | bit;
                node = 2 * node + 1 + bit;
            }
            d_idxT[(size_t)c * Nn + n] = (unsigned char)kidx;
        }
    }
}

// ---------------- K2: HMMA one-hot GEMM  out = E @ (Lhi + Llo) ----------------
#define S2_BPK  0
#define S2_IDX  131072
#define S2_SMEM (S2_IDX + Cc * 128)   // 139264

#define NSPLIT 8
#define NPER   (Nn / NSPLIT)          // 4096

__global__ __launch_bounds__(256) void k_lutmma(float* __restrict__ out)
{
    extern __shared__ char sm[];
    unsigned* Bpk = (unsigned*)(sm + S2_BPK);           // [mt4][c64][lane32][4]
    unsigned char* idxs = (unsigned char*)(sm + S2_IDX);

    int tid  = threadIdx.x;
    int wid  = tid >> 5;
    int lane = tid & 31;
    int g    = lane >> 2;
    int t4   = lane & 3;

    int mBase  = blockIdx.x * 32;
    int nRange = blockIdx.y * NPER;

    // ---- copy packed B slice (contiguous 128 KB) ----
    {
        const uint4* src = (const uint4*)&d_Lpk[(size_t)(mBase >> 3) * Cc * 32 * 4];
        uint4* dst = (uint4*)Bpk;
        for (int i = tid; i < 8192; i += 256) dst[i] = src[i];
    }
    __syncthreads();

    int n0loc = wid * 16 + g;
    for (int it = 0; it < NPER / 128; it++) {
        int nb = nRange + it * 128;
        {
            int c = tid >> 2, off = (tid & 3) * 32;
            *(uint4*)&idxs[c * 128 + off] =
                *(const uint4*)&d_idxT[(size_t)c * Nn + nb + off];
            *(uint4*)&idxs[c * 128 + off + 16] =
                *(const uint4*)&d_idxT[(size_t)c * Nn + nb + off + 16];
        }
        __syncthreads();

        float acc[4][4];
#pragma unroll
        for (int ms = 0; ms < 4; ms++)
#pragma unroll
            for (int q = 0; q < 4; q++) acc[ms][q] = 0.f;

#pragma unroll 4
        for (int c = 0; c < Cc; c++) {
            unsigned i0 = idxs[c * 128 + n0loc];
            unsigned i1 = idxs[c * 128 + n0loc + 8];
            unsigned s0 = 0x3F80u << ((i0 & 1) << 4);
            unsigned s1 = 0x3F80u << ((i1 & 1) << 4);
            unsigned h0 = i0 >> 1, h1 = i1 >> 1;
            unsigned a0 = (h0 == (unsigned)t4)     ? s0 : 0u;
            unsigned a1 = (h1 == (unsigned)t4)     ? s1 : 0u;
            unsigned a2 = (h0 == (unsigned)t4 + 4) ? s0 : 0u;
            unsigned a3 = (h1 == (unsigned)t4 + 4) ? s1 : 0u;

#pragma unroll
            for (int ms = 0; ms < 4; ms++) {
                uint4 q4 = *(const uint4*)&Bpk[(((ms * Cc + c) * 32) + lane) * 4];
                asm volatile(
                    "mma.sync.aligned.m16n8k16.row.col.f32.bf16.bf16.f32 "
                    "{%0,%1,%2,%3}, {%4,%5,%6,%7}, {%8,%9}, {%0,%1,%2,%3};"
                    : "+f"(acc[ms][0]), "+f"(acc[ms][1]), "+f"(acc[ms][2]), "+f"(acc[ms][3])
                    : "r"(a0), "r"(a1), "r"(a2), "r"(a3), "r"(q4.x), "r"(q4.y));
                asm volatile(
                    "mma.sync.aligned.m16n8k16.row.col.f32.bf16.bf16.f32 "
                    "{%0,%1,%2,%3}, {%4,%5,%6,%7}, {%8,%9}, {%0,%1,%2,%3};"
                    : "+f"(acc[ms][0]), "+f"(acc[ms][1]), "+f"(acc[ms][2]), "+f"(acc[ms][3])
                    : "r"(a0), "r"(a1), "r"(a2), "r"(a3), "r"(q4.z), "r"(q4.w));
            }
        }

        int nA = nb + n0loc;
#pragma unroll
        for (int ms = 0; ms < 4; ms++) {
            float2 v0 = make_float2(acc[ms][0], acc[ms][1]);
            float2 v1 = make_float2(acc[ms][2], acc[ms][3]);
            *(float2*)&out[(size_t)nA * Mm + mBase + ms * 8 + t4 * 2] = v0;
            *(float2*)&out[(size_t)(nA + 8) * Mm + mBase + ms * 8 + t4 * 2] = v1;
        }
        __syncthreads();
    }
}

// ---------------- launch ----------------
extern "C" void kernel_launch(void* const* d_in, const int* in_sizes, int n_in,
                              void* d_out, int out_size) {
    const float *I = nullptr, *T = nullptr, *L = nullptr, *A = nullptr;
    for (int i = 0; i < n_in; i++) {
        switch (in_sizes[i]) {
            case Nn * Dd:      I = (const float*)d_in[i]; break;
            case 960:          T = (const float*)d_in[i]; break;
            case Mm * Cc * Kk: L = (const float*)d_in[i]; break;
            case Dd * Jj:      A = (const float*)d_in[i]; break;
            default: break;  // S, B unused — tree structure hardcoded
        }
    }
    float* out = (float*)d_out;

    cudaFuncSetAttribute(k_gemm_tf32, cudaFuncAttributeMaxDynamicSharedMemorySize, G1_SMEM);
    cudaFuncSetAttribute(k_lutmma,    cudaFuncAttributeMaxDynamicSharedMemorySize, S2_SMEM);

    k_pack<<<(Mm * Cc * Kk / 2) / 256, 256>>>(L);

    dim3 g1(Jj / 64, Nn / 128);     // (4, 256)
    k_gemm_tf32<<<g1, 256, G1_SMEM>>>(I, A, T);

    k_fixup<<<64, 256>>>(I, A, T);

    dim3 g2(Mm / 32, NSPLIT);       // (16, 8)
    k_lutmma<<<g2, 256, S2_SMEM>>>(out);
}

// round 6
// speedup vs baseline: 1.5570x; 1.5570x over previous
#include <cuda_runtime.h>
#include <cuda_bf16.h>
#include <cstdint>

#define Nn 32768
#define Dd 512
#define Cc 64
#define Kk 16
#define Mm 512
#define Jj 256   // C*DEPTH

// ---------------- scratch ----------------
__device__ unsigned char d_idxT[Cc * Nn];            // [c][n]  2 MB
__device__ unsigned d_Lpk[64 * Cc * 32 * 4];         // packed B frags (bh0,bh1,bl0,bl1) 2 MB

// ---------------- K_pack: L -> packed bf16 hi/lo fragment layout ----------------
__global__ void k_pack(const float* __restrict__ L) {
    int i = blockIdx.x * 256 + threadIdx.x;        // pair index over 512*512
    int m = i >> 9;
    int k = (i & 511) * 2;
    float2 f = *(const float2*)&L[(size_t)m * 1024 + k];
    __nv_bfloat16 h0 = __float2bfloat16(f.x), h1 = __float2bfloat16(f.y);
    __nv_bfloat16 l0 = __float2bfloat16(f.x - __bfloat162float(h0));
    __nv_bfloat16 l1 = __float2bfloat16(f.y - __bfloat162float(h1));
    unsigned hv = ((unsigned)*(unsigned short*)&h1 << 16) | *(unsigned short*)&h0;
    unsigned lv = ((unsigned)*(unsigned short*)&l1 << 16) | *(unsigned short*)&l0;
    int c = k >> 4, kk = k & 15;
    int t4 = (kk >> 1) & 3, rb = kk >> 3;
    int lane = (m & 7) * 4 + t4, mt = m >> 3;
    unsigned* base = &d_Lpk[(((mt * Cc + c) * 32) + lane) * 4];
    base[rb] = hv;
    base[2 + rb] = lv;
}

// ---------------- K1: fused fp32 GEMM (P = I @ A) + tree traversal -> idxT ----------------
__device__ __forceinline__ unsigned trav(const float* __restrict__ Tc,
                                         float f0, float f1, float f2, float f3) {
    float f[4] = {f0, f1, f2, f3};
    unsigned node = 0, k = 0;
#pragma unroll
    for (int l = 0; l < 4; l++) {
        unsigned bit = (f[l] > __ldg(&Tc[node])) ? 1u : 0u;
        k = (k << 1) | bit;
        node = 2 * node + 1 + bit;
    }
    return k;
}

#define BM 128
#define BN 128
#define BK 32

__global__ __launch_bounds__(256) void k_gemm_tree(
    const float* __restrict__ I, const float* __restrict__ A,
    const float* __restrict__ T)
{
    __shared__ float Is[BK][132];
    __shared__ float As[BK][BN];

    int tid = threadIdx.x;
    int tx = tid & 15;
    int ty = tid >> 4;
    int rowBase = blockIdx.y * BM;
    int colBase = blockIdx.x * BN;

    int r  = tid >> 3;
    int kv = tid & 7;
    int kk = tid >> 5;
    int jv = tid & 31;

    unsigned long long acc[8][4];
#pragma unroll
    for (int i = 0; i < 8; i++)
#pragma unroll
        for (int j = 0; j < 4; j++) acc[i][j] = 0ull;

    for (int kt = 0; kt < Dd; kt += BK) {
#pragma unroll
        for (int q = 0; q < 4; q++) {
            int lr = r + q * 32;
            float4 v = *(const float4*)&I[(size_t)(rowBase + lr) * Dd + kt + kv * 4];
            Is[kv * 4 + 0][lr] = v.x;
            Is[kv * 4 + 1][lr] = v.y;
            Is[kv * 4 + 2][lr] = v.z;
            Is[kv * 4 + 3][lr] = v.w;
        }
#pragma unroll
        for (int q = 0; q < 4; q++)
            *(float4*)&As[kk + q * 8][jv * 4] =
                *(const float4*)&A[(size_t)(kt + kk + q * 8) * Jj + colBase + jv * 4];
        __syncthreads();

#pragma unroll 8
        for (int kx = 0; kx < BK; kx++) {
            float4 a01 = *(const float4*)&Is[kx][ty * 8];
            float4 a23 = *(const float4*)&Is[kx][ty * 8 + 4];
            ulonglong2 b0 = *(const ulonglong2*)&As[kx][tx * 4];
            ulonglong2 b1 = *(const ulonglong2*)&As[kx][64 + tx * 4];
            unsigned long long bp[4] = {b0.x, b0.y, b1.x, b1.y};
            float av[8] = {a01.x, a01.y, a01.z, a01.w, a23.x, a23.y, a23.z, a23.w};
#pragma unroll
            for (int i = 0; i < 8; i++) {
                unsigned long long ap;
                asm("mov.b64 %0, {%1, %2};" : "=l"(ap) : "f"(av[i]), "f"(av[i]));
#pragma unroll
                for (int j = 0; j < 4; j++)
                    asm("fma.rn.f32x2 %0, %1, %2, %0;"
                        : "+l"(acc[i][j]) : "l"(ap), "l"(bp[j]));
            }
        }
        __syncthreads();
    }

    int cbBase = colBase >> 2;
    int cb0 = cbBase + tx;
    int cb1 = cbBase + 16 + tx;
    unsigned long long p0 = 0, p1 = 0;
#pragma unroll
    for (int i = 0; i < 8; i++) {
        float f[8];
#pragma unroll
        for (int j = 0; j < 4; j++)
            asm("mov.b64 {%0, %1}, %2;" : "=f"(f[2 * j]), "=f"(f[2 * j + 1]) : "l"(acc[i][j]));
        unsigned k1 = trav(&T[cb0 * 15], f[0], f[1], f[2], f[3]);
        unsigned k2 = trav(&T[cb1 * 15], f[4], f[5], f[6], f[7]);
        p0 |= (unsigned long long)k1 << (8 * i);
        p1 |= (unsigned long long)k2 << (8 * i);
    }
    int nb = rowBase + ty * 8;
    *(unsigned long long*)&d_idxT[(size_t)cb0 * Nn + nb] = p0;
    *(unsigned long long*)&d_idxT[(size_t)cb1 * Nn + nb] = p1;
}

// ---------------- K2: HMMA one-hot GEMM  out = E @ (Lhi + Llo), 512 threads ----------------
#define S2_BPK  0
#define S2_IDX  131072
#define S2_SMEM (S2_IDX + Cc * 256)   // 147456

#define NSPLIT 8
#define NPER   (Nn / NSPLIT)          // 4096
#define NROWS  256                    // rows per iteration (16 warps x 16)

__global__ __launch_bounds__(512) void k_lutmma(float* __restrict__ out)
{
    extern __shared__ char sm[];
    unsigned* Bpk = (unsigned*)(sm + S2_BPK);           // [mt4][c64][lane32][4]
    unsigned char* idxs = (unsigned char*)(sm + S2_IDX);

    int tid  = threadIdx.x;
    int wid  = tid >> 5;       // 0..15
    int lane = tid & 31;
    int g    = lane >> 2;
    int t4   = lane & 3;

    int mBase  = blockIdx.x * 32;
    int nRange = blockIdx.y * NPER;

    // ---- copy packed B slice (contiguous 128 KB) ----
    {
        const uint4* src = (const uint4*)&d_Lpk[(size_t)(mBase >> 3) * Cc * 32 * 4];
        uint4* dst = (uint4*)Bpk;
        for (int i = tid; i < 8192; i += 512) dst[i] = src[i];
    }
    __syncthreads();

    int n0loc = wid * 16 + g;   // 0..255
    for (int it = 0; it < NPER / NROWS; it++) {
        int nb = nRange + it * NROWS;
        // ---- load idx tile: 64 c x 256 n bytes ----
        {
            int c = tid >> 3, off = (tid & 7) * 32;
            *(uint4*)&idxs[c * NROWS + off] =
                *(const uint4*)&d_idxT[(size_t)c * Nn + nb + off];
            *(uint4*)&idxs[c * NROWS + off + 16] =
                *(const uint4*)&d_idxT[(size_t)c * Nn + nb + off + 16];
        }
        __syncthreads();

        float acc[4][4];
#pragma unroll
        for (int ms = 0; ms < 4; ms++)
#pragma unroll
            for (int q = 0; q < 4; q++) acc[ms][q] = 0.f;

#pragma unroll 4
        for (int c = 0; c < Cc; c++) {
            unsigned i0 = idxs[c * NROWS + n0loc];
            unsigned i1 = idxs[c * NROWS + n0loc + 8];
            unsigned s0 = 0x3F80u << ((i0 & 1) << 4);
            unsigned s1 = 0x3F80u << ((i1 & 1) << 4);
            unsigned h0 = i0 >> 1, h1 = i1 >> 1;
            unsigned a0 = (h0 == (unsigned)t4)     ? s0 : 0u;
            unsigned a1 = (h1 == (unsigned)t4)     ? s1 : 0u;
            unsigned a2 = (h0 == (unsigned)t4 + 4) ? s0 : 0u;
            unsigned a3 = (h1 == (unsigned)t4 + 4) ? s1 : 0u;

#pragma unroll
            for (int ms = 0; ms < 4; ms++) {
                uint4 q4 = *(const uint4*)&Bpk[(((ms * Cc + c) * 32) + lane) * 4];
                asm volatile(
                    "mma.sync.aligned.m16n8k16.row.col.f32.bf16.bf16.f32 "
                    "{%0,%1,%2,%3}, {%4,%5,%6,%7}, {%8,%9}, {%0,%1,%2,%3};"
                    : "+f"(acc[ms][0]), "+f"(acc[ms][1]), "+f"(acc[ms][2]), "+f"(acc[ms][3])
                    : "r"(a0), "r"(a1), "r"(a2), "r"(a3), "r"(q4.x), "r"(q4.y));
                asm volatile(
                    "mma.sync.aligned.m16n8k16.row.col.f32.bf16.bf16.f32 "
                    "{%0,%1,%2,%3}, {%4,%5,%6,%7}, {%8,%9}, {%0,%1,%2,%3};"
                    : "+f"(acc[ms][0]), "+f"(acc[ms][1]), "+f"(acc[ms][2]), "+f"(acc[ms][3])
                    : "r"(a0), "r"(a1), "r"(a2), "r"(a3), "r"(q4.z), "r"(q4.w));
            }
        }

        int nA = nb + n0loc;
#pragma unroll
        for (int ms = 0; ms < 4; ms++) {
            float2 v0 = make_float2(acc[ms][0], acc[ms][1]);
            float2 v1 = make_float2(acc[ms][2], acc[ms][3]);
            *(float2*)&out[(size_t)nA * Mm + mBase + ms * 8 + t4 * 2] = v0;
            *(float2*)&out[(size_t)(nA + 8) * Mm + mBase + ms * 8 + t4 * 2] = v1;
        }
        __syncthreads();
    }
}

// ---------------- launch ----------------
extern "C" void kernel_launch(void* const* d_in, const int* in_sizes, int n_in,
                              void* d_out, int out_size) {
    const float *I = nullptr, *T = nullptr, *L = nullptr, *A = nullptr;
    for (int i = 0; i < n_in; i++) {
        switch (in_sizes[i]) {
            case Nn * Dd:      I = (const float*)d_in[i]; break;
            case 960:          T = (const float*)d_in[i]; break;
            case Mm * Cc * Kk: L = (const float*)d_in[i]; break;
            case Dd * Jj:      A = (const float*)d_in[i]; break;
            default: break;  // S, B unused — tree structure hardcoded
        }
    }
    float* out = (float*)d_out;

    cudaFuncSetAttribute(k_lutmma, cudaFuncAttributeMaxDynamicSharedMemorySize, S2_SMEM);

    k_pack<<<(Mm * Cc * Kk / 2) / 256, 256>>>(L);

    dim3 g1(Jj / BN, Nn / BM);      // (2, 256)
    k_gemm_tree<<<g1, 256>>>(I, A, T);

    dim3 g2(Mm / 32, NSPLIT);       // (16, 8)
    k_lutmma<<<g2, 512, S2_SMEM>>>(out);
}